// round 11
// baseline (speedup 1.0000x reference)
#include <cuda_runtime.h>
#include <cuda_fp16.h>
#include <math.h>
#include <stdint.h>

#define B_   8
#define C_   256
#define HW_  4096
#define CO_  256
#define OCF_ 18
#define K_   9
#define NCHUNK 36            // 9 taps x 4 c-chunks of 64

__device__ float g_offset[B_ * OCF_ * HW_];
__device__ __half g_wsw[NCHUNK * 16384];            // pre-swizzled W chunks [36][256o x 64c]
__device__ __half g_patch[256 * NCHUNK * 8192];     // pre-swizzled P chunks [slice][36][128p x 64c]
__device__ float g_y[B_ * CO_ * HW_];

__device__ __forceinline__ uint32_t smem_u32(const void* p) {
    uint32_t a;
    asm("{ .reg .u64 t; cvta.to.shared.u64 t, %1; cvt.u32.u64 %0, t; }" : "=r"(a) : "l"(p));
    return a;
}
__device__ __forceinline__ uint32_t swz(uint32_t b) { return b ^ ((b >> 3) & 0x70); }
__device__ __forceinline__ void ldsm4(uint32_t* r, uint32_t addr) {
    asm volatile("ldmatrix.sync.aligned.m8n8.x4.shared.b16 {%0,%1,%2,%3}, [%4];"
        : "=r"(r[0]), "=r"(r[1]), "=r"(r[2]), "=r"(r[3]) : "r"(addr));
}
__device__ __forceinline__ void mma_f16(float* d, const uint32_t* a, const uint32_t* b) {
    asm volatile("mma.sync.aligned.m16n8k16.row.col.f32.f16.f16.f32 "
        "{%0,%1,%2,%3}, {%4,%5,%6,%7}, {%8,%9}, {%0,%1,%2,%3};"
        : "+f"(d[0]), "+f"(d[1]), "+f"(d[2]), "+f"(d[3])
        : "r"(a[0]), "r"(a[1]), "r"(a[2]), "r"(a[3]), "r"(b[0]), "r"(b[1]));
}
__device__ __forceinline__ void fma2(unsigned long long& d,
                                     unsigned long long a, unsigned long long b) {
    asm("fma.rn.f32x2 %0, %1, %2, %0;" : "+l"(d) : "l"(a), "l"(b));
}
__device__ __forceinline__ unsigned long long pack2(float lo, float hi) {
    unsigned long long r;
    asm("mov.b64 %0, {%1, %2};" : "=l"(r) : "f"(lo), "f"(hi));
    return r;
}
__device__ __forceinline__ void unpack2(float& lo, float& hi, unsigned long long v) {
    asm("mov.b64 {%0, %1}, %2;" : "=f"(lo), "=f"(hi) : "l"(v));
}
#define CP16(dst, src) asm volatile("cp.async.cg.shared.global [%0], [%1], 16;" :: "r"(dst), "l"(src))
#define CP_COMMIT()    asm volatile("cp.async.commit_group;" ::: "memory")
#define CP_WAIT(n)     asm volatile("cp.async.wait_group %0;" :: "n"(n) : "memory")

// GEMM smem: 3 stages of 48KB (P 16K | W 32K)
#define STAGE_BYTES 49152
#define OFF_P       0
#define OFF_W       16384
#define NSTAGE      3
#define SMEM_TOTAL  (NSTAGE * STAGE_BYTES)

// ---------------------------------------------------------------------------
// Kernel 0: dw [o][c][k] fp32 -> g_wsw pre-swizzled fp16 chunks
// ---------------------------------------------------------------------------
__global__ void __launch_bounds__(256) wt_prep_kernel(const float* __restrict__ dw) {
    int e = blockIdx.x * 256 + threadIdx.x;          // 0..589823
    int c = e & 255;
    int o = (e >> 8) & 255;
    int k = e >> 16;
    float v = dw[((size_t)o * C_ + c) * K_ + k];
    int chunk = k * 4 + (c >> 6);
    int cc = c & 63;
    uint32_t sw = swz((uint32_t)(o * 128 + cc * 2));
    g_wsw[chunk * 16384 + (sw >> 1)] = __float2half(v);
}

// ---------------------------------------------------------------------------
// Kernel 1: offset conv (unchanged, f32x2)
// ---------------------------------------------------------------------------
__global__ void __launch_bounds__(256) offset_conv_kernel(const float* __restrict__ x,
                                                          const float* __restrict__ ow) {
    __shared__ float w_s[64 * 180];
    int tid = threadIdx.x;
    int gid = blockIdx.x * 256 + tid;
    int b   = gid >> 12;
    int rem = gid & 4095;
    int ho  = rem >> 6, wo = rem & 63;

    unsigned long long acc2[10];
#pragma unroll
    for (int i = 0; i < 10; i++) acc2[i] = 0ull;

    int xoff[9];
#pragma unroll
    for (int kh = 0; kh < 3; kh++)
#pragma unroll
        for (int kw = 0; kw < 3; kw++) {
            int y = ho - 1 + kh, xx = wo - 1 + kw;
            bool v = ((unsigned)y < 64u) && ((unsigned)xx < 64u);
            xoff[kh * 3 + kw] = v ? (y * 64 + xx) : -1;
        }
    const float* xb = x + (size_t)b * C_ * HW_;

    for (int c0 = 0; c0 < C_; c0 += 64) {
        __syncthreads();
        for (int i = tid; i < 64 * 180; i += 256) {
            int cc = i / 180, r = i % 180, tap = r / 20, ch = r % 20;
            w_s[i] = (ch < 18) ? ow[((size_t)ch * C_ + (c0 + cc)) * K_ + tap] : 0.f;
        }
        __syncthreads();
        for (int cc = 0; cc < 64; cc++) {
            const float* xp = xb + (size_t)(c0 + cc) * HW_;
            float xv[9];
#pragma unroll
            for (int t = 0; t < 9; t++) xv[t] = (xoff[t] >= 0) ? xp[xoff[t]] : 0.f;
            const float* wb = &w_s[cc * 180];
#pragma unroll
            for (int t = 0; t < 9; t++) {
                unsigned long long v2 = pack2(xv[t], xv[t]);
#pragma unroll
                for (int q = 0; q < 5; q++) {
                    ulonglong2 w2 = *(const ulonglong2*)(wb + t * 20 + q * 4);
                    fma2(acc2[q * 2],     v2, w2.x);
                    fma2(acc2[q * 2 + 1], v2, w2.y);
                }
            }
        }
    }
#pragma unroll
    for (int j = 0; j < 9; j++) {
        float lo, hi;
        unpack2(lo, hi, acc2[j]);
        g_offset[((size_t)b * OCF_ + 2 * j)     * HW_ + rem] = lo;
        g_offset[((size_t)b * OCF_ + 2 * j + 1) * HW_ + rem] = hi;
    }
}

// ---------------------------------------------------------------------------
// Kernel 2: gather — block = (slice, tap). Writes pre-swizzled fp16 patch
// chunks to g_patch. High occupancy hides LDG latency.
// ---------------------------------------------------------------------------
__global__ void __launch_bounds__(256) gather_kernel(const float* __restrict__ x) {
    __shared__ float samp_w[128 * 4];
    __shared__ int   samp_i[128 * 4];
    int tid = threadIdx.x;
    int blk = blockIdx.x;                 // 0..2303
    int k     = blk % 9;
    int slice = blk / 9;                  // b*32 + rp
    int b  = slice >> 5;
    int rp = slice & 31;
    int ho0 = rp * 2;

    if (tid < 128) {
        int p = tid;
        int ho = ho0 + (p >> 6), wo2 = p & 63;
        const float* offp = g_offset + (size_t)b * OCF_ * HW_ + ho * 64 + wo2;
        float dy = offp[(size_t)(2 * k) * HW_];
        float dx = offp[(size_t)(2 * k + 1) * HW_];
        float sy = (float)(ho - 1 + k / 3) + dy;
        float sx = (float)(wo2 - 1 + k % 3) + dx;
        float y0f = floorf(sy), x0f = floorf(sx);
        float ly = sy - y0f, lx = sx - x0f;
        int y0 = (int)y0f, x0 = (int)x0f;
#pragma unroll
        for (int j = 0; j < 4; j++) {
            int yc = y0 + (j >> 1), xc = x0 + (j & 1);
            float wy = (j >> 1) ? ly : 1.f - ly;
            float wx = (j & 1)  ? lx : 1.f - lx;
            bool v = ((unsigned)yc < 64u) && ((unsigned)xc < 64u);
            samp_w[p * 4 + j] = v ? wy * wx : 0.f;
            samp_i[p * 4 + j] = min(max(yc, 0), 63) * 64 + min(max(xc, 0), 63);
        }
    }
    __syncthreads();

    const float* xb = x + (size_t)b * C_ * HW_;
    int p  = tid & 127;
    int c8base = (tid >> 7) * 4;          // 0 or 4
    const float4 wv = *(const float4*)(samp_w + p * 4);
    const int4   iv = *(const int4*)(samp_i + p * 4);

    // 4 c-chunks x (c8base..c8base+3) groups of 8 channels
#pragma unroll 1
    for (int ci = 0; ci < 4; ci++) {
        char* dst = (char*)(g_patch + ((size_t)slice * NCHUNK + k * 4 + ci) * 8192);
#pragma unroll
        for (int g = 0; g < 4; g++) {
            int c8 = c8base + g;
            uint32_t hp[4];
#pragma unroll
            for (int j = 0; j < 4; j++) {
                const float* xp0 = xb + (size_t)(ci * 64 + c8 * 8 + j * 2) * HW_;
                const float* xp1 = xp0 + HW_;
                float v0 = wv.x * xp0[iv.x] + wv.y * xp0[iv.y]
                         + wv.z * xp0[iv.z] + wv.w * xp0[iv.w];
                float v1 = wv.x * xp1[iv.x] + wv.y * xp1[iv.y]
                         + wv.z * xp1[iv.z] + wv.w * xp1[iv.w];
                __half2 h2 = __floats2half2_rn(v0, v1);
                hp[j] = *(uint32_t*)&h2;
            }
            uint32_t sw = swz((uint32_t)(p * 128 + c8 * 16));
            *(uint4*)(dst + sw) = *(uint4*)hp;
        }
    }
}

// ---------------------------------------------------------------------------
// Kernel 3: dense GEMM — CTA=(b,rp): D[256o][128p]; 8 warps 4(o)x2(p) 64x64.
// 3-stage cp.async pipeline, all loads linear.
// ---------------------------------------------------------------------------
__global__ void __launch_bounds__(256, 1) gemm_kernel() {
    extern __shared__ char smem[];
    uint32_t sb = smem_u32(smem);
    int tid = threadIdx.x, wid = tid >> 5, lane = tid & 31;
    int blk = blockIdx.x;                 // slice
    int b   = blk >> 5;
    int rp  = blk & 31;
    int pos0 = rp * 128;
    int wo = wid >> 1;
    int wp = wid & 1;
    int mat = lane >> 3, mr = lane & 7;

    const char* psrc = (const char*)(g_patch + (size_t)blk * NCHUNK * 8192);

    float acc[4][8][4];
#pragma unroll
    for (int i = 0; i < 4; i++)
#pragma unroll
        for (int j = 0; j < 8; j++)
#pragma unroll
            for (int q = 0; q < 4; q++) acc[i][j][q] = 0.f;

    // prefetch issue for one chunk into stage st
    auto prefetch = [&](int chunk, int st) {
        uint32_t sdst = sb + (uint32_t)st * STAGE_BYTES;
        const char* ps = psrc + (size_t)chunk * 16384;
        const char* ws = (const char*)g_wsw + (size_t)chunk * 32768;
#pragma unroll
        for (int i = 0; i < 4; i++)       // P: 16KB = 1024 x 16B
            CP16(sdst + OFF_P + (tid + i * 256) * 16, ps + (tid + i * 256) * 16);
#pragma unroll
        for (int i = 0; i < 8; i++)       // W: 32KB = 2048 x 16B
            CP16(sdst + OFF_W + (tid + i * 256) * 16, ws + (tid + i * 256) * 16);
        CP_COMMIT();
    };

    prefetch(0, 0);
    prefetch(1, 1);

#pragma unroll 1
    for (int chunk = 0; chunk < NCHUNK; chunk++) {
        int st = chunk % NSTAGE;
        CP_WAIT(1);                       // stage st complete
        __syncthreads();                  // all warps see it; prev compute done

        if (chunk + 2 < NCHUNK)
            prefetch(chunk + 2, (chunk + 2) % NSTAGE);

        uint32_t cur = sb + (uint32_t)st * STAGE_BYTES;
#pragma unroll
        for (int ks = 0; ks < 4; ks++) {
            uint32_t af[4][4];
#pragma unroll
            for (int mt = 0; mt < 4; mt++) {
                uint32_t byte = (uint32_t)((wo * 64 + mt * 16 + (mat & 1) * 8 + mr) * 128
                                           + ks * 32 + (mat >> 1) * 16);
                ldsm4(af[mt], cur + OFF_W + swz(byte));
            }
            uint32_t bf[4][4];
#pragma unroll
            for (int nb = 0; nb < 4; nb++) {
                uint32_t byte = (uint32_t)((wp * 64 + nb * 16 + (mat >> 1) * 8 + mr) * 128
                                           + ks * 32 + (mat & 1) * 16);
                ldsm4(bf[nb], cur + OFF_P + swz(byte));
            }
#pragma unroll
            for (int nb = 0; nb < 4; nb++)
#pragma unroll
                for (int half = 0; half < 2; half++)
#pragma unroll
                    for (int mt = 0; mt < 4; mt++)
                        mma_f16(acc[mt][2 * nb + half], af[mt], bf[nb] + 2 * half);
        }
        __syncthreads();                  // compute done before stage reuse
    }

    int l4 = lane >> 2, l2 = (lane & 3) * 2;
#pragma unroll
    for (int mt = 0; mt < 4; mt++) {
#pragma unroll
        for (int nt = 0; nt < 8; nt++) {
            int o = wo * 64 + mt * 16 + l4;
            int p = wp * 64 + nt * 8 + l2;
            float* dst = g_y + ((size_t)(b * CO_ + o)) * HW_ + pos0 + p;
            *(float2*)dst = make_float2(acc[mt][nt][0], acc[mt][nt][1]);
            *(float2*)(dst + (size_t)8 * HW_) = make_float2(acc[mt][nt][2], acc[mt][nt][3]);
        }
    }
}

// ---------------------------------------------------------------------------
// Kernel 4: channel attention
// ---------------------------------------------------------------------------
__global__ void __launch_bounds__(256) attn_kernel(float* __restrict__ out) {
    int bo = blockIdx.x;
    const float4* yp = (const float4*)(g_y + (size_t)bo * HW_);
    int tid = threadIdx.x;

    float s = 0.f, s2 = 0.f;
    float4 v[4];
#pragma unroll
    for (int i = 0; i < 4; i++) {
        v[i] = yp[tid + i * 256];
        s  += v[i].x + v[i].y + v[i].z + v[i].w;
        s2 += v[i].x * v[i].x + v[i].y * v[i].y + v[i].z * v[i].z + v[i].w * v[i].w;
    }
#pragma unroll
    for (int off = 16; off; off >>= 1) {
        s  += __shfl_down_sync(0xffffffffu, s,  off);
        s2 += __shfl_down_sync(0xffffffffu, s2, off);
    }
    __shared__ float rs[8], rs2[8];
    __shared__ float sa;
    int lane = tid & 31, w = tid >> 5;
    if (lane == 0) { rs[w] = s; rs2[w] = s2; }
    __syncthreads();
    if (tid == 0) {
        float S = 0.f, S2 = 0.f;
#pragma unroll
        for (int i = 0; i < 8; i++) { S += rs[i]; S2 += rs2[i]; }
        float mean = S * (1.f / 4096.f);
        float var  = (S2 - S * S * (1.f / 4096.f)) * (1.f / 4095.f);
        float sd   = sqrtf(fmaxf(var, 0.f));
        sa = 1.f / (1.f + expf(-(mean + sd)));
    }
    __syncthreads();
    float a = sa;
    float4* op = (float4*)(out + (size_t)bo * HW_);
#pragma unroll
    for (int i = 0; i < 4; i++) {
        float4 u = v[i];
        u.x *= a; u.y *= a; u.z *= a; u.w *= a;
        op[tid + i * 256] = u;
    }
}

// ---------------------------------------------------------------------------
extern "C" void kernel_launch(void* const* d_in, const int* in_sizes, int n_in,
                              void* d_out, int out_size) {
    const float* x  = (const float*)d_in[0];
    const float* ow = (const float*)d_in[1];
    const float* dw = (const float*)d_in[2];
    float* out = (float*)d_out;

    cudaFuncSetAttribute(gemm_kernel,
                         cudaFuncAttributeMaxDynamicSharedMemorySize, SMEM_TOTAL);

    wt_prep_kernel<<<(K_ * CO_ * C_) / 256, 256>>>(dw);
    offset_conv_kernel<<<(B_ * HW_) / 256, 256>>>(x, ow);
    gather_kernel<<<256 * K_, 256>>>(x);
    gemm_kernel<<<256, 256, SMEM_TOTAL>>>();
    attn_kernel<<<B_ * CO_, 256>>>(out);
}

// round 14
// speedup vs baseline: 1.3494x; 1.3494x over previous
#include <cuda_runtime.h>
#include <cuda_fp16.h>
#include <math.h>
#include <stdint.h>

#define B_   8
#define C_   256
#define HW_  4096
#define CO_  256
#define OCF_ 18
#define K_   9
#define NCHUNK 36            // 9 taps x 4 c-chunks of 64

__device__ float g_offset[B_ * OCF_ * HW_];
__device__ __half g_wsw[NCHUNK * 16384];            // pre-swizzled W chunks [36][256o x 64c]
__device__ __half g_xt[B_ * HW_ * C_];              // channels-last fp16 x [b][hw][c]
__device__ __half g_patch[256 * NCHUNK * 8192];     // pre-swizzled P chunks [slice][36][128p x 64c]
__device__ float g_y[B_ * CO_ * HW_];

__device__ __forceinline__ uint32_t smem_u32(const void* p) {
    uint32_t a;
    asm("{ .reg .u64 t; cvta.to.shared.u64 t, %1; cvt.u32.u64 %0, t; }" : "=r"(a) : "l"(p));
    return a;
}
__device__ __forceinline__ uint32_t swz(uint32_t b) { return b ^ ((b >> 3) & 0x70); }
__device__ __forceinline__ void ldsm4(uint32_t* r, uint32_t addr) {
    asm volatile("ldmatrix.sync.aligned.m8n8.x4.shared.b16 {%0,%1,%2,%3}, [%4];"
        : "=r"(r[0]), "=r"(r[1]), "=r"(r[2]), "=r"(r[3]) : "r"(addr));
}
__device__ __forceinline__ void mma_f16(float* d, const uint32_t* a, const uint32_t* b) {
    asm volatile("mma.sync.aligned.m16n8k16.row.col.f32.f16.f16.f32 "
        "{%0,%1,%2,%3}, {%4,%5,%6,%7}, {%8,%9}, {%0,%1,%2,%3};"
        : "+f"(d[0]), "+f"(d[1]), "+f"(d[2]), "+f"(d[3])
        : "r"(a[0]), "r"(a[1]), "r"(a[2]), "r"(a[3]), "r"(b[0]), "r"(b[1]));
}
__device__ __forceinline__ void fma2(unsigned long long& d,
                                     unsigned long long a, unsigned long long b) {
    asm("fma.rn.f32x2 %0, %1, %2, %0;" : "+l"(d) : "l"(a), "l"(b));
}
__device__ __forceinline__ unsigned long long pack2(float lo, float hi) {
    unsigned long long r;
    asm("mov.b64 %0, {%1, %2};" : "=l"(r) : "f"(lo), "f"(hi));
    return r;
}
__device__ __forceinline__ void unpack2(float& lo, float& hi, unsigned long long v) {
    asm("mov.b64 {%0, %1}, %2;" : "=f"(lo), "=f"(hi) : "l"(v));
}
#define CP16(dst, src) asm volatile("cp.async.cg.shared.global [%0], [%1], 16;" :: "r"(dst), "l"(src))
#define CP_COMMIT()    asm volatile("cp.async.commit_group;" ::: "memory")
#define CP_WAIT(n)     asm volatile("cp.async.wait_group %0;" :: "n"(n) : "memory")

// GEMM smem: 3 stages of 48KB (P 16K | W 32K)
#define STAGE_BYTES 49152
#define OFF_P       0
#define OFF_W       16384
#define NSTAGE      3
#define SMEM_TOTAL  (NSTAGE * STAGE_BYTES)

// ---------------------------------------------------------------------------
// Kernel 0: dw [o][c][k] -> g_wsw pre-swizzled fp16 chunks
// ---------------------------------------------------------------------------
__global__ void __launch_bounds__(256) wt_prep_kernel(const float* __restrict__ dw) {
    int e = blockIdx.x * 256 + threadIdx.x;
    int c = e & 255;
    int o = (e >> 8) & 255;
    int k = e >> 16;
    float v = dw[((size_t)o * C_ + c) * K_ + k];
    int chunk = k * 4 + (c >> 6);
    int cc = c & 63;
    uint32_t sw = swz((uint32_t)(o * 128 + cc * 2));
    g_wsw[chunk * 16384 + (sw >> 1)] = __float2half(v);
}

// ---------------------------------------------------------------------------
// Kernel 1: transpose x [B,C,H,W] fp32 -> g_xt [B,H,W,C] fp16
// block = (b, y). FIXED: write ALL 2048 16B pieces (was 512 -> only c<64).
// ---------------------------------------------------------------------------
__global__ void __launch_bounds__(256) xt_kernel(const float* __restrict__ x) {
    __shared__ __half tile[64 * 264];
    int tid = threadIdx.x;
    int blk = blockIdx.x;
    int b = blk >> 6, y = blk & 63;
    int c = tid;

    const float* src = x + ((size_t)(b * 256 + c) * HW_ + y * 64);
#pragma unroll
    for (int w4 = 0; w4 < 16; w4++) {
        float4 v = *(const float4*)(src + w4 * 4);
        tile[(w4 * 4 + 0) * 264 + c] = __float2half(v.x);
        tile[(w4 * 4 + 1) * 264 + c] = __float2half(v.y);
        tile[(w4 * 4 + 2) * 264 + c] = __float2half(v.z);
        tile[(w4 * 4 + 3) * 264 + c] = __float2half(v.w);
    }
    __syncthreads();
    char* dst = (char*)g_xt + ((size_t)b * HW_ + y * 64) * 512;
#pragma unroll
    for (int i = 0; i < 8; i++) {
        int e = tid + i * 256;            // 0..2047 = 64 w x 32 sub
        int w = e >> 5, sub = e & 31;     // sub covers full 256 channels
        uint4 v = *(const uint4*)&tile[w * 264 + sub * 8];
        *(uint4*)(dst + (size_t)w * 512 + sub * 16) = v;
    }
}

// ---------------------------------------------------------------------------
// Kernel 2: offset conv (unchanged)
// ---------------------------------------------------------------------------
__global__ void __launch_bounds__(256) offset_conv_kernel(const float* __restrict__ x,
                                                          const float* __restrict__ ow) {
    __shared__ float w_s[64 * 180];
    int tid = threadIdx.x;
    int gid = blockIdx.x * 256 + tid;
    int b   = gid >> 12;
    int rem = gid & 4095;
    int ho  = rem >> 6, wo = rem & 63;

    unsigned long long acc2[10];
#pragma unroll
    for (int i = 0; i < 10; i++) acc2[i] = 0ull;

    int xoff[9];
#pragma unroll
    for (int kh = 0; kh < 3; kh++)
#pragma unroll
        for (int kw = 0; kw < 3; kw++) {
            int y = ho - 1 + kh, xx = wo - 1 + kw;
            bool v = ((unsigned)y < 64u) && ((unsigned)xx < 64u);
            xoff[kh * 3 + kw] = v ? (y * 64 + xx) : -1;
        }
    const float* xb = x + (size_t)b * C_ * HW_;

    for (int c0 = 0; c0 < C_; c0 += 64) {
        __syncthreads();
        for (int i = tid; i < 64 * 180; i += 256) {
            int cc = i / 180, r = i % 180, tap = r / 20, ch = r % 20;
            w_s[i] = (ch < 18) ? ow[((size_t)ch * C_ + (c0 + cc)) * K_ + tap] : 0.f;
        }
        __syncthreads();
        for (int cc = 0; cc < 64; cc++) {
            const float* xp = xb + (size_t)(c0 + cc) * HW_;
            float xv[9];
#pragma unroll
            for (int t = 0; t < 9; t++) xv[t] = (xoff[t] >= 0) ? xp[xoff[t]] : 0.f;
            const float* wb = &w_s[cc * 180];
#pragma unroll
            for (int t = 0; t < 9; t++) {
                unsigned long long v2 = pack2(xv[t], xv[t]);
#pragma unroll
                for (int q = 0; q < 5; q++) {
                    ulonglong2 w2 = *(const ulonglong2*)(wb + t * 20 + q * 4);
                    fma2(acc2[q * 2],     v2, w2.x);
                    fma2(acc2[q * 2 + 1], v2, w2.y);
                }
            }
        }
    }
#pragma unroll
    for (int j = 0; j < 9; j++) {
        float lo, hi;
        unpack2(lo, hi, acc2[j]);
        g_offset[((size_t)b * OCF_ + 2 * j)     * HW_ + rem] = lo;
        g_offset[((size_t)b * OCF_ + 2 * j + 1) * HW_ + rem] = hi;
    }
}

// ---------------------------------------------------------------------------
// Kernel 3: gather — coalesced 16B channel-row pieces from g_xt.
// block = (slice, tap); thread = (p8, sub): p = pp*32+p8, channels sub*8..+7.
// ---------------------------------------------------------------------------
__global__ void __launch_bounds__(256) gather_kernel() {
    __shared__ float samp_w[128 * 4];
    __shared__ int   samp_i[128 * 4];
    int tid = threadIdx.x;
    int blk = blockIdx.x;                 // 0..2303
    int k     = blk % 9;
    int slice = blk / 9;
    int b  = slice >> 5;
    int rp = slice & 31;
    int ho0 = rp * 2;

    if (tid < 128) {
        int p = tid;
        int ho = ho0 + (p >> 6), wo2 = p & 63;
        const float* offp = g_offset + (size_t)b * OCF_ * HW_ + ho * 64 + wo2;
        float dy = offp[(size_t)(2 * k) * HW_];
        float dx = offp[(size_t)(2 * k + 1) * HW_];
        float sy = (float)(ho - 1 + k / 3) + dy;
        float sx = (float)(wo2 - 1 + k % 3) + dx;
        float y0f = floorf(sy), x0f = floorf(sx);
        float ly = sy - y0f, lx = sx - x0f;
        int y0 = (int)y0f, x0 = (int)x0f;
#pragma unroll
        for (int j = 0; j < 4; j++) {
            int yc = y0 + (j >> 1), xc = x0 + (j & 1);
            float wy = (j >> 1) ? ly : 1.f - ly;
            float wx = (j & 1)  ? lx : 1.f - lx;
            bool v = ((unsigned)yc < 64u) && ((unsigned)xc < 64u);
            samp_w[p * 4 + j] = v ? wy * wx : 0.f;
            samp_i[p * 4 + j] = min(max(yc, 0), 63) * 64 + min(max(xc, 0), 63);
        }
    }
    __syncthreads();

    const char* xtb = (const char*)g_xt + (size_t)b * HW_ * 512;
    int p8 = tid >> 3, sub = tid & 7;

#pragma unroll 1
    for (int pp = 0; pp < 4; pp++) {
        int p = pp * 32 + p8;
        const float4 wv = *(const float4*)(samp_w + p * 4);
        const int4   iv = *(const int4*)(samp_i + p * 4);
        const char* r0 = xtb + (size_t)iv.x * 512 + sub * 16;
        const char* r1 = xtb + (size_t)iv.y * 512 + sub * 16;
        const char* r2 = xtb + (size_t)iv.z * 512 + sub * 16;
        const char* r3 = xtb + (size_t)iv.w * 512 + sub * 16;
#pragma unroll
        for (int ci = 0; ci < 4; ci++) {
            uint4 cA = *(const uint4*)(r0 + ci * 128);
            uint4 cB = *(const uint4*)(r1 + ci * 128);
            uint4 cC = *(const uint4*)(r2 + ci * 128);
            uint4 cD = *(const uint4*)(r3 + ci * 128);
            float v[8];
#pragma unroll
            for (int i = 0; i < 8; i++) v[i] = 0.f;
            const uint4* crs[4] = { &cA, &cB, &cC, &cD };
#pragma unroll
            for (int j = 0; j < 4; j++) {
                const __half2* h = (const __half2*)crs[j];
                float wj = (&wv.x)[j];
#pragma unroll
                for (int q = 0; q < 4; q++) {
                    float2 f = __half22float2(h[q]);
                    v[2 * q]     += wj * f.x;
                    v[2 * q + 1] += wj * f.y;
                }
            }
            uint32_t hp[4];
#pragma unroll
            for (int q = 0; q < 4; q++) {
                __half2 h2 = __floats2half2_rn(v[2 * q], v[2 * q + 1]);
                hp[q] = *(uint32_t*)&h2;
            }
            char* dst = (char*)(g_patch + ((size_t)slice * NCHUNK + k * 4 + ci) * 8192);
            *(uint4*)(dst + swz((uint32_t)(p * 128 + sub * 16))) = *(uint4*)hp;
        }
    }
}

// ---------------------------------------------------------------------------
// Kernel 4: dense GEMM (R11 verbatim) — 3-stage cp.async, all loads linear.
// ---------------------------------------------------------------------------
__global__ void __launch_bounds__(256, 1) gemm_kernel() {
    extern __shared__ char smem[];
    uint32_t sb = smem_u32(smem);
    int tid = threadIdx.x, wid = tid >> 5, lane = tid & 31;
    int blk = blockIdx.x;
    int b   = blk >> 5;
    int rp  = blk & 31;
    int pos0 = rp * 128;
    int wo = wid >> 1;
    int wp = wid & 1;
    int mat = lane >> 3, mr = lane & 7;

    const char* psrc = (const char*)(g_patch + (size_t)blk * NCHUNK * 8192);

    float acc[4][8][4];
#pragma unroll
    for (int i = 0; i < 4; i++)
#pragma unroll
        for (int j = 0; j < 8; j++)
#pragma unroll
            for (int q = 0; q < 4; q++) acc[i][j][q] = 0.f;

    auto prefetch = [&](int chunk, int st) {
        uint32_t sdst = sb + (uint32_t)st * STAGE_BYTES;
        const char* ps = psrc + (size_t)chunk * 16384;
        const char* ws = (const char*)g_wsw + (size_t)chunk * 32768;
#pragma unroll
        for (int i = 0; i < 4; i++)
            CP16(sdst + OFF_P + (tid + i * 256) * 16, ps + (tid + i * 256) * 16);
#pragma unroll
        for (int i = 0; i < 8; i++)
            CP16(sdst + OFF_W + (tid + i * 256) * 16, ws + (tid + i * 256) * 16);
        CP_COMMIT();
    };

    prefetch(0, 0);
    prefetch(1, 1);

#pragma unroll 1
    for (int chunk = 0; chunk < NCHUNK; chunk++) {
        int st = chunk % NSTAGE;
        CP_WAIT(1);
        __syncthreads();

        if (chunk + 2 < NCHUNK)
            prefetch(chunk + 2, (chunk + 2) % NSTAGE);

        uint32_t cur = sb + (uint32_t)st * STAGE_BYTES;
#pragma unroll
        for (int ks = 0; ks < 4; ks++) {
            uint32_t af[4][4];
#pragma unroll
            for (int mt = 0; mt < 4; mt++) {
                uint32_t byte = (uint32_t)((wo * 64 + mt * 16 + (mat & 1) * 8 + mr) * 128
                                           + ks * 32 + (mat >> 1) * 16);
                ldsm4(af[mt], cur + OFF_W + swz(byte));
            }
            uint32_t bf[4][4];
#pragma unroll
            for (int nb = 0; nb < 4; nb++) {
                uint32_t byte = (uint32_t)((wp * 64 + nb * 16 + (mat >> 1) * 8 + mr) * 128
                                           + ks * 32 + (mat & 1) * 16);
                ldsm4(bf[nb], cur + OFF_P + swz(byte));
            }
#pragma unroll
            for (int nb = 0; nb < 4; nb++)
#pragma unroll
                for (int half = 0; half < 2; half++)
#pragma unroll
                    for (int mt = 0; mt < 4; mt++)
                        mma_f16(acc[mt][2 * nb + half], af[mt], bf[nb] + 2 * half);
        }
        __syncthreads();
    }

    int l4 = lane >> 2, l2 = (lane & 3) * 2;
#pragma unroll
    for (int mt = 0; mt < 4; mt++) {
#pragma unroll
        for (int nt = 0; nt < 8; nt++) {
            int o = wo * 64 + mt * 16 + l4;
            int p = wp * 64 + nt * 8 + l2;
            float* dst = g_y + ((size_t)(b * CO_ + o)) * HW_ + pos0 + p;
            *(float2*)dst = make_float2(acc[mt][nt][0], acc[mt][nt][1]);
            *(float2*)(dst + (size_t)8 * HW_) = make_float2(acc[mt][nt][2], acc[mt][nt][3]);
        }
    }
}

// ---------------------------------------------------------------------------
// Kernel 5: channel attention (unchanged)
// ---------------------------------------------------------------------------
__global__ void __launch_bounds__(256) attn_kernel(float* __restrict__ out) {
    int bo = blockIdx.x;
    const float4* yp = (const float4*)(g_y + (size_t)bo * HW_);
    int tid = threadIdx.x;

    float s = 0.f, s2 = 0.f;
    float4 v[4];
#pragma unroll
    for (int i = 0; i < 4; i++) {
        v[i] = yp[tid + i * 256];
        s  += v[i].x + v[i].y + v[i].z + v[i].w;
        s2 += v[i].x * v[i].x + v[i].y * v[i].y + v[i].z * v[i].z + v[i].w * v[i].w;
    }
#pragma unroll
    for (int off = 16; off; off >>= 1) {
        s  += __shfl_down_sync(0xffffffffu, s,  off);
        s2 += __shfl_down_sync(0xffffffffu, s2, off);
    }
    __shared__ float rs[8], rs2[8];
    __shared__ float sa;
    int lane = tid & 31, w = tid >> 5;
    if (lane == 0) { rs[w] = s; rs2[w] = s2; }
    __syncthreads();
    if (tid == 0) {
        float S = 0.f, S2 = 0.f;
#pragma unroll
        for (int i = 0; i < 8; i++) { S += rs[i]; S2 += rs2[i]; }
        float mean = S * (1.f / 4096.f);
        float var  = (S2 - S * S * (1.f / 4096.f)) * (1.f / 4095.f);
        float sd   = sqrtf(fmaxf(var, 0.f));
        sa = 1.f / (1.f + expf(-(mean + sd)));
    }
    __syncthreads();
    float a = sa;
    float4* op = (float4*)(out + (size_t)bo * HW_);
#pragma unroll
    for (int i = 0; i < 4; i++) {
        float4 u = v[i];
        u.x *= a; u.y *= a; u.z *= a; u.w *= a;
        op[tid + i * 256] = u;
    }
}

// ---------------------------------------------------------------------------
extern "C" void kernel_launch(void* const* d_in, const int* in_sizes, int n_in,
                              void* d_out, int out_size) {
    const float* x  = (const float*)d_in[0];
    const float* ow = (const float*)d_in[1];
    const float* dw = (const float*)d_in[2];
    float* out = (float*)d_out;

    cudaFuncSetAttribute(gemm_kernel,
                         cudaFuncAttributeMaxDynamicSharedMemorySize, SMEM_TOTAL);

    wt_prep_kernel<<<(K_ * CO_ * C_) / 256, 256>>>(dw);
    xt_kernel<<<B_ * 64, 256>>>(x);
    offset_conv_kernel<<<(B_ * HW_) / 256, 256>>>(x, ow);
    gather_kernel<<<256 * K_, 256>>>();
    gemm_kernel<<<256, 256, SMEM_TOTAL>>>();
    attn_kernel<<<B_ * CO_, 256>>>(out);
}

// round 15
// speedup vs baseline: 1.3874x; 1.0282x over previous
#include <cuda_runtime.h>
#include <cuda_fp16.h>
#include <math.h>
#include <stdint.h>

#define B_   8
#define C_   256
#define HW_  4096
#define CO_  256
#define OCF_ 18
#define K_   9
#define NCHUNK 36            // 9 taps x 4 c-chunks of 64

__device__ float g_offset[B_ * OCF_ * HW_];
__device__ __half g_wsw[NCHUNK * 16384];            // pre-swizzled W chunks [36][256o x 64c]
__device__ __half g_xt[B_ * HW_ * C_];              // channels-last fp16 x [b][hw][c]
__device__ __half g_patch[256 * NCHUNK * 8192];     // pre-swizzled P chunks [slice][36][128p x 64c]
__device__ float g_y[B_ * CO_ * HW_];

__device__ __forceinline__ uint32_t smem_u32(const void* p) {
    uint32_t a;
    asm("{ .reg .u64 t; cvta.to.shared.u64 t, %1; cvt.u32.u64 %0, t; }" : "=r"(a) : "l"(p));
    return a;
}
__device__ __forceinline__ uint32_t swz(uint32_t b) { return b ^ ((b >> 3) & 0x70); }
__device__ __forceinline__ void ldsm4(uint32_t* r, uint32_t addr) {
    asm volatile("ldmatrix.sync.aligned.m8n8.x4.shared.b16 {%0,%1,%2,%3}, [%4];"
        : "=r"(r[0]), "=r"(r[1]), "=r"(r[2]), "=r"(r[3]) : "r"(addr));
}
__device__ __forceinline__ void mma_f16(float* d, const uint32_t* a, const uint32_t* b) {
    asm volatile("mma.sync.aligned.m16n8k16.row.col.f32.f16.f16.f32 "
        "{%0,%1,%2,%3}, {%4,%5,%6,%7}, {%8,%9}, {%0,%1,%2,%3};"
        : "+f"(d[0]), "+f"(d[1]), "+f"(d[2]), "+f"(d[3])
        : "r"(a[0]), "r"(a[1]), "r"(a[2]), "r"(a[3]), "r"(b[0]), "r"(b[1]));
}
__device__ __forceinline__ void fma2(unsigned long long& d,
                                     unsigned long long a, unsigned long long b) {
    asm("fma.rn.f32x2 %0, %1, %2, %0;" : "+l"(d) : "l"(a), "l"(b));
}
__device__ __forceinline__ unsigned long long pack2(float lo, float hi) {
    unsigned long long r;
    asm("mov.b64 %0, {%1, %2};" : "=l"(r) : "f"(lo), "f"(hi));
    return r;
}
__device__ __forceinline__ void unpack2(float& lo, float& hi, unsigned long long v) {
    asm("mov.b64 {%0, %1}, %2;" : "=f"(lo), "=f"(hi) : "l"(v));
}
#define CP16(dst, src) asm volatile("cp.async.cg.shared.global [%0], [%1], 16;" :: "r"(dst), "l"(src))
#define CP_COMMIT()    asm volatile("cp.async.commit_group;" ::: "memory")
#define CP_WAIT(n)     asm volatile("cp.async.wait_group %0;" :: "n"(n) : "memory")

// GEMM smem: 3 stages of 32KB (P 16K | W 16K) — o-split halves W per CTA
#define STAGE_BYTES 32768
#define OFF_P       0
#define OFF_W       16384
#define NSTAGE      3
#define SMEM_TOTAL  (NSTAGE * STAGE_BYTES)

// ---------------------------------------------------------------------------
// Kernel 0: dw [o][c][k] -> g_wsw pre-swizzled fp16 chunks
// ---------------------------------------------------------------------------
__global__ void __launch_bounds__(256) wt_prep_kernel(const float* __restrict__ dw) {
    int e = blockIdx.x * 256 + threadIdx.x;
    int c = e & 255;
    int o = (e >> 8) & 255;
    int k = e >> 16;
    float v = dw[((size_t)o * C_ + c) * K_ + k];
    int chunk = k * 4 + (c >> 6);
    int cc = c & 63;
    uint32_t sw = swz((uint32_t)(o * 128 + cc * 2));
    g_wsw[chunk * 16384 + (sw >> 1)] = __float2half(v);
}

// ---------------------------------------------------------------------------
// Kernel 1: transpose x [B,C,H,W] fp32 -> g_xt [B,H,W,C] fp16 (R14-fixed)
// ---------------------------------------------------------------------------
__global__ void __launch_bounds__(256) xt_kernel(const float* __restrict__ x) {
    __shared__ __half tile[64 * 264];
    int tid = threadIdx.x;
    int blk = blockIdx.x;
    int b = blk >> 6, y = blk & 63;
    int c = tid;

    const float* src = x + ((size_t)(b * 256 + c) * HW_ + y * 64);
#pragma unroll
    for (int w4 = 0; w4 < 16; w4++) {
        float4 v = *(const float4*)(src + w4 * 4);
        tile[(w4 * 4 + 0) * 264 + c] = __float2half(v.x);
        tile[(w4 * 4 + 1) * 264 + c] = __float2half(v.y);
        tile[(w4 * 4 + 2) * 264 + c] = __float2half(v.z);
        tile[(w4 * 4 + 3) * 264 + c] = __float2half(v.w);
    }
    __syncthreads();
    char* dst = (char*)g_xt + ((size_t)b * HW_ + y * 64) * 512;
#pragma unroll
    for (int i = 0; i < 8; i++) {
        int e = tid + i * 256;            // 0..2047 = 64 w x 32 sub
        int w = e >> 5, sub = e & 31;
        uint4 v = *(const uint4*)&tile[w * 264 + sub * 8];
        *(uint4*)(dst + (size_t)w * 512 + sub * 16) = v;
    }
}

// ---------------------------------------------------------------------------
// Kernel 2: offset conv (unchanged)
// ---------------------------------------------------------------------------
__global__ void __launch_bounds__(256) offset_conv_kernel(const float* __restrict__ x,
                                                          const float* __restrict__ ow) {
    __shared__ float w_s[64 * 180];
    int tid = threadIdx.x;
    int gid = blockIdx.x * 256 + tid;
    int b   = gid >> 12;
    int rem = gid & 4095;
    int ho  = rem >> 6, wo = rem & 63;

    unsigned long long acc2[10];
#pragma unroll
    for (int i = 0; i < 10; i++) acc2[i] = 0ull;

    int xoff[9];
#pragma unroll
    for (int kh = 0; kh < 3; kh++)
#pragma unroll
        for (int kw = 0; kw < 3; kw++) {
            int y = ho - 1 + kh, xx = wo - 1 + kw;
            bool v = ((unsigned)y < 64u) && ((unsigned)xx < 64u);
            xoff[kh * 3 + kw] = v ? (y * 64 + xx) : -1;
        }
    const float* xb = x + (size_t)b * C_ * HW_;

    for (int c0 = 0; c0 < C_; c0 += 64) {
        __syncthreads();
        for (int i = tid; i < 64 * 180; i += 256) {
            int cc = i / 180, r = i % 180, tap = r / 20, ch = r % 20;
            w_s[i] = (ch < 18) ? ow[((size_t)ch * C_ + (c0 + cc)) * K_ + tap] : 0.f;
        }
        __syncthreads();
        for (int cc = 0; cc < 64; cc++) {
            const float* xp = xb + (size_t)(c0 + cc) * HW_;
            float xv[9];
#pragma unroll
            for (int t = 0; t < 9; t++) xv[t] = (xoff[t] >= 0) ? xp[xoff[t]] : 0.f;
            const float* wb = &w_s[cc * 180];
#pragma unroll
            for (int t = 0; t < 9; t++) {
                unsigned long long v2 = pack2(xv[t], xv[t]);
#pragma unroll
                for (int q = 0; q < 5; q++) {
                    ulonglong2 w2 = *(const ulonglong2*)(wb + t * 20 + q * 4);
                    fma2(acc2[q * 2],     v2, w2.x);
                    fma2(acc2[q * 2 + 1], v2, w2.y);
                }
            }
        }
    }
#pragma unroll
    for (int j = 0; j < 9; j++) {
        float lo, hi;
        unpack2(lo, hi, acc2[j]);
        g_offset[((size_t)b * OCF_ + 2 * j)     * HW_ + rem] = lo;
        g_offset[((size_t)b * OCF_ + 2 * j + 1) * HW_ + rem] = hi;
    }
}

// ---------------------------------------------------------------------------
// Kernel 3: gather (R14 verbatim) — coalesced g_xt channel rows -> g_patch
// ---------------------------------------------------------------------------
__global__ void __launch_bounds__(256) gather_kernel() {
    __shared__ float samp_w[128 * 4];
    __shared__ int   samp_i[128 * 4];
    int tid = threadIdx.x;
    int blk = blockIdx.x;                 // 0..2303
    int k     = blk % 9;
    int slice = blk / 9;
    int b  = slice >> 5;
    int rp = slice & 31;
    int ho0 = rp * 2;

    if (tid < 128) {
        int p = tid;
        int ho = ho0 + (p >> 6), wo2 = p & 63;
        const float* offp = g_offset + (size_t)b * OCF_ * HW_ + ho * 64 + wo2;
        float dy = offp[(size_t)(2 * k) * HW_];
        float dx = offp[(size_t)(2 * k + 1) * HW_];
        float sy = (float)(ho - 1 + k / 3) + dy;
        float sx = (float)(wo2 - 1 + k % 3) + dx;
        float y0f = floorf(sy), x0f = floorf(sx);
        float ly = sy - y0f, lx = sx - x0f;
        int y0 = (int)y0f, x0 = (int)x0f;
#pragma unroll
        for (int j = 0; j < 4; j++) {
            int yc = y0 + (j >> 1), xc = x0 + (j & 1);
            float wy = (j >> 1) ? ly : 1.f - ly;
            float wx = (j & 1)  ? lx : 1.f - lx;
            bool v = ((unsigned)yc < 64u) && ((unsigned)xc < 64u);
            samp_w[p * 4 + j] = v ? wy * wx : 0.f;
            samp_i[p * 4 + j] = min(max(yc, 0), 63) * 64 + min(max(xc, 0), 63);
        }
    }
    __syncthreads();

    const char* xtb = (const char*)g_xt + (size_t)b * HW_ * 512;
    int p8 = tid >> 3, sub = tid & 7;

#pragma unroll 1
    for (int pp = 0; pp < 4; pp++) {
        int p = pp * 32 + p8;
        const float4 wv = *(const float4*)(samp_w + p * 4);
        const int4   iv = *(const int4*)(samp_i + p * 4);
        const char* r0 = xtb + (size_t)iv.x * 512 + sub * 16;
        const char* r1 = xtb + (size_t)iv.y * 512 + sub * 16;
        const char* r2 = xtb + (size_t)iv.z * 512 + sub * 16;
        const char* r3 = xtb + (size_t)iv.w * 512 + sub * 16;
#pragma unroll
        for (int ci = 0; ci < 4; ci++) {
            uint4 cA = *(const uint4*)(r0 + ci * 128);
            uint4 cB = *(const uint4*)(r1 + ci * 128);
            uint4 cC = *(const uint4*)(r2 + ci * 128);
            uint4 cD = *(const uint4*)(r3 + ci * 128);
            float v[8];
#pragma unroll
            for (int i = 0; i < 8; i++) v[i] = 0.f;
            const uint4* crs[4] = { &cA, &cB, &cC, &cD };
#pragma unroll
            for (int j = 0; j < 4; j++) {
                const __half2* h = (const __half2*)crs[j];
                float wj = (&wv.x)[j];
#pragma unroll
                for (int q = 0; q < 4; q++) {
                    float2 f = __half22float2(h[q]);
                    v[2 * q]     += wj * f.x;
                    v[2 * q + 1] += wj * f.y;
                }
            }
            uint32_t hp[4];
#pragma unroll
            for (int q = 0; q < 4; q++) {
                __half2 h2 = __floats2half2_rn(v[2 * q], v[2 * q + 1]);
                hp[q] = *(uint32_t*)&h2;
            }
            char* dst = (char*)(g_patch + ((size_t)slice * NCHUNK + k * 4 + ci) * 8192);
            *(uint4*)(dst + swz((uint32_t)(p * 128 + sub * 16))) = *(uint4*)hp;
        }
    }
}

// ---------------------------------------------------------------------------
// Kernel 4: dense GEMM, o-split x2: CTA=(slice, half) computes D[128o][128p].
// 512 CTAs, 2 CTAs/SM. 8 warps = 4(o)x2(p), warp tile 32o x 64p.
// ---------------------------------------------------------------------------
__global__ void __launch_bounds__(256, 2) gemm_kernel() {
    extern __shared__ char smem[];
    uint32_t sb = smem_u32(smem);
    int tid = threadIdx.x, wid = tid >> 5, lane = tid & 31;
    int blk = blockIdx.x;                 // 0..511
    int slice = blk >> 1;
    int half  = blk & 1;
    int b   = slice >> 5;
    int rp  = slice & 31;
    int pos0 = rp * 128;
    int wo = wid >> 1;                    // o quarter of 128 -> 32 outs
    int wp = wid & 1;
    int mat = lane >> 3, mr = lane & 7;

    const char* psrc = (const char*)(g_patch + (size_t)slice * NCHUNK * 8192);

    float acc[2][8][4];
#pragma unroll
    for (int i = 0; i < 2; i++)
#pragma unroll
        for (int j = 0; j < 8; j++)
#pragma unroll
            for (int q = 0; q < 4; q++) acc[i][j][q] = 0.f;

    auto prefetch = [&](int chunk, int st) {
        uint32_t sdst = sb + (uint32_t)st * STAGE_BYTES;
        const char* ps = psrc + (size_t)chunk * 16384;
        const char* ws = (const char*)g_wsw + (size_t)chunk * 32768 + (size_t)half * 16384;
#pragma unroll
        for (int i = 0; i < 4; i++)
            CP16(sdst + OFF_P + (tid + i * 256) * 16, ps + (tid + i * 256) * 16);
#pragma unroll
        for (int i = 0; i < 4; i++)
            CP16(sdst + OFF_W + (tid + i * 256) * 16, ws + (tid + i * 256) * 16);
        CP_COMMIT();
    };

    prefetch(0, 0);
    prefetch(1, 1);

#pragma unroll 1
    for (int chunk = 0; chunk < NCHUNK; chunk++) {
        int st = chunk % NSTAGE;
        CP_WAIT(1);
        __syncthreads();

        if (chunk + 2 < NCHUNK)
            prefetch(chunk + 2, (chunk + 2) % NSTAGE);

        uint32_t cur = sb + (uint32_t)st * STAGE_BYTES;
#pragma unroll
        for (int ks = 0; ks < 4; ks++) {
            uint32_t af[2][4];
#pragma unroll
            for (int mt = 0; mt < 2; mt++) {
                uint32_t byte = (uint32_t)((wo * 32 + mt * 16 + (mat & 1) * 8 + mr) * 128
                                           + ks * 32 + (mat >> 1) * 16);
                ldsm4(af[mt], cur + OFF_W + swz(byte));
            }
            uint32_t bf[4][4];
#pragma unroll
            for (int nb = 0; nb < 4; nb++) {
                uint32_t byte = (uint32_t)((wp * 64 + nb * 16 + (mat >> 1) * 8 + mr) * 128
                                           + ks * 32 + (mat & 1) * 16);
                ldsm4(bf[nb], cur + OFF_P + swz(byte));
            }
#pragma unroll
            for (int nb = 0; nb < 4; nb++)
#pragma unroll
                for (int hf = 0; hf < 2; hf++)
#pragma unroll
                    for (int mt = 0; mt < 2; mt++)
                        mma_f16(acc[mt][2 * nb + hf], af[mt], bf[nb] + 2 * hf);
        }
        __syncthreads();
    }

    int l4 = lane >> 2, l2 = (lane & 3) * 2;
#pragma unroll
    for (int mt = 0; mt < 2; mt++) {
#pragma unroll
        for (int nt = 0; nt < 8; nt++) {
            int o = half * 128 + wo * 32 + mt * 16 + l4;
            int p = wp * 64 + nt * 8 + l2;
            float* dst = g_y + ((size_t)(b * CO_ + o)) * HW_ + pos0 + p;
            *(float2*)dst = make_float2(acc[mt][nt][0], acc[mt][nt][1]);
            *(float2*)(dst + (size_t)8 * HW_) = make_float2(acc[mt][nt][2], acc[mt][nt][3]);
        }
    }
}

// ---------------------------------------------------------------------------
// Kernel 5: channel attention (unchanged)
// ---------------------------------------------------------------------------
__global__ void __launch_bounds__(256) attn_kernel(float* __restrict__ out) {
    int bo = blockIdx.x;
    const float4* yp = (const float4*)(g_y + (size_t)bo * HW_);
    int tid = threadIdx.x;

    float s = 0.f, s2 = 0.f;
    float4 v[4];
#pragma unroll
    for (int i = 0; i < 4; i++) {
        v[i] = yp[tid + i * 256];
        s  += v[i].x + v[i].y + v[i].z + v[i].w;
        s2 += v[i].x * v[i].x + v[i].y * v[i].y + v[i].z * v[i].z + v[i].w * v[i].w;
    }
#pragma unroll
    for (int off = 16; off; off >>= 1) {
        s  += __shfl_down_sync(0xffffffffu, s,  off);
        s2 += __shfl_down_sync(0xffffffffu, s2, off);
    }
    __shared__ float rs[8], rs2[8];
    __shared__ float sa;
    int lane = tid & 31, w = tid >> 5;
    if (lane == 0) { rs[w] = s; rs2[w] = s2; }
    __syncthreads();
    if (tid == 0) {
        float S = 0.f, S2 = 0.f;
#pragma unroll
        for (int i = 0; i < 8; i++) { S += rs[i]; S2 += rs2[i]; }
        float mean = S * (1.f / 4096.f);
        float var  = (S2 - S * S * (1.f / 4096.f)) * (1.f / 4095.f);
        float sd   = sqrtf(fmaxf(var, 0.f));
        sa = 1.f / (1.f + expf(-(mean + sd)));
    }
    __syncthreads();
    float a = sa;
    float4* op = (float4*)(out + (size_t)bo * HW_);
#pragma unroll
    for (int i = 0; i < 4; i++) {
        float4 u = v[i];
        u.x *= a; u.y *= a; u.z *= a; u.w *= a;
        op[tid + i * 256] = u;
    }
}

// ---------------------------------------------------------------------------
extern "C" void kernel_launch(void* const* d_in, const int* in_sizes, int n_in,
                              void* d_out, int out_size) {
    const float* x  = (const float*)d_in[0];
    const float* ow = (const float*)d_in[1];
    const float* dw = (const float*)d_in[2];
    float* out = (float*)d_out;

    cudaFuncSetAttribute(gemm_kernel,
                         cudaFuncAttributeMaxDynamicSharedMemorySize, SMEM_TOTAL);

    wt_prep_kernel<<<(K_ * CO_ * C_) / 256, 256>>>(dw);
    xt_kernel<<<B_ * 64, 256>>>(x);
    offset_conv_kernel<<<(B_ * HW_) / 256, 256>>>(x, ow);
    gather_kernel<<<256 * K_, 256>>>();
    gemm_kernel<<<512, 256, SMEM_TOTAL>>>();
    attn_kernel<<<B_ * CO_, 256>>>(out);
}

// round 16
// speedup vs baseline: 1.5904x; 1.1463x over previous
#include <cuda_runtime.h>
#include <cuda_fp16.h>
#include <math.h>
#include <stdint.h>

#define B_   8
#define C_   256
#define HW_  4096
#define CO_  256
#define OCF_ 18
#define K_   9
#define NCHUNK 36            // 9 taps x 4 c-chunks of 64

__device__ float g_offpart[2][B_ * OCF_ * HW_];     // channel-half partial offsets
__device__ __half g_wsw[NCHUNK * 16384];            // pre-swizzled W chunks [36][256o x 64c]
__device__ __half g_xt[B_ * HW_ * C_];              // channels-last fp16 x [b][hw][c]
__device__ __half g_patch[256 * NCHUNK * 8192];     // pre-swizzled P chunks [slice][36][128p x 64c]
__device__ float g_y[B_ * CO_ * HW_];

__device__ __forceinline__ uint32_t smem_u32(const void* p) {
    uint32_t a;
    asm("{ .reg .u64 t; cvta.to.shared.u64 t, %1; cvt.u32.u64 %0, t; }" : "=r"(a) : "l"(p));
    return a;
}
__device__ __forceinline__ uint32_t swz(uint32_t b) { return b ^ ((b >> 3) & 0x70); }
__device__ __forceinline__ void ldsm4(uint32_t* r, uint32_t addr) {
    asm volatile("ldmatrix.sync.aligned.m8n8.x4.shared.b16 {%0,%1,%2,%3}, [%4];"
        : "=r"(r[0]), "=r"(r[1]), "=r"(r[2]), "=r"(r[3]) : "r"(addr));
}
__device__ __forceinline__ void mma_f16(float* d, const uint32_t* a, const uint32_t* b) {
    asm volatile("mma.sync.aligned.m16n8k16.row.col.f32.f16.f16.f32 "
        "{%0,%1,%2,%3}, {%4,%5,%6,%7}, {%8,%9}, {%0,%1,%2,%3};"
        : "+f"(d[0]), "+f"(d[1]), "+f"(d[2]), "+f"(d[3])
        : "r"(a[0]), "r"(a[1]), "r"(a[2]), "r"(a[3]), "r"(b[0]), "r"(b[1]));
}
__device__ __forceinline__ void fma2(unsigned long long& d,
                                     unsigned long long a, unsigned long long b) {
    asm("fma.rn.f32x2 %0, %1, %2, %0;" : "+l"(d) : "l"(a), "l"(b));
}
__device__ __forceinline__ unsigned long long pack2(float lo, float hi) {
    unsigned long long r;
    asm("mov.b64 %0, {%1, %2};" : "=l"(r) : "f"(lo), "f"(hi));
    return r;
}
__device__ __forceinline__ void unpack2(float& lo, float& hi, unsigned long long v) {
    asm("mov.b64 {%0, %1}, %2;" : "=f"(lo), "=f"(hi) : "l"(v));
}
#define CP16(dst, src) asm volatile("cp.async.cg.shared.global [%0], [%1], 16;" :: "r"(dst), "l"(src))
#define CP_COMMIT()    asm volatile("cp.async.commit_group;" ::: "memory")
#define CP_WAIT(n)     asm volatile("cp.async.wait_group %0;" :: "n"(n) : "memory")

// GEMM smem: 3 stages of 32KB (P 16K | W 16K) — o-split x2
#define STAGE_BYTES 32768
#define OFF_P       0
#define OFF_W       16384
#define NSTAGE      3
#define SMEM_TOTAL  (NSTAGE * STAGE_BYTES)

// ---------------------------------------------------------------------------
// Kernel 0: dw [o][c][k] -> g_wsw pre-swizzled fp16 chunks
// ---------------------------------------------------------------------------
__global__ void __launch_bounds__(256) wt_prep_kernel(const float* __restrict__ dw) {
    int e = blockIdx.x * 256 + threadIdx.x;
    int c = e & 255;
    int o = (e >> 8) & 255;
    int k = e >> 16;
    float v = dw[((size_t)o * C_ + c) * K_ + k];
    int chunk = k * 4 + (c >> 6);
    int cc = c & 63;
    uint32_t sw = swz((uint32_t)(o * 128 + cc * 2));
    g_wsw[chunk * 16384 + (sw >> 1)] = __float2half(v);
}

// ---------------------------------------------------------------------------
// Kernel 1: transpose x [B,C,H,W] fp32 -> g_xt [B,H,W,C] fp16
// ---------------------------------------------------------------------------
__global__ void __launch_bounds__(256) xt_kernel(const float* __restrict__ x) {
    __shared__ __half tile[64 * 264];
    int tid = threadIdx.x;
    int blk = blockIdx.x;
    int b = blk >> 6, y = blk & 63;
    int c = tid;

    const float* src = x + ((size_t)(b * 256 + c) * HW_ + y * 64);
#pragma unroll
    for (int w4 = 0; w4 < 16; w4++) {
        float4 v = *(const float4*)(src + w4 * 4);
        tile[(w4 * 4 + 0) * 264 + c] = __float2half(v.x);
        tile[(w4 * 4 + 1) * 264 + c] = __float2half(v.y);
        tile[(w4 * 4 + 2) * 264 + c] = __float2half(v.z);
        tile[(w4 * 4 + 3) * 264 + c] = __float2half(v.w);
    }
    __syncthreads();
    char* dst = (char*)g_xt + ((size_t)b * HW_ + y * 64) * 512;
#pragma unroll
    for (int i = 0; i < 8; i++) {
        int e = tid + i * 256;            // 0..2047 = 64 w x 32 sub
        int w = e >> 5, sub = e & 31;
        uint4 v = *(const uint4*)&tile[w * 264 + sub * 8];
        *(uint4*)(dst + (size_t)w * 512 + sub * 16) = v;
    }
}

// ---------------------------------------------------------------------------
// Kernel 2: offset conv, C-SPLIT x2: block = (posblk, half). Each block sums
// channels [half*128, half*128+128) for 256 positions -> g_offpart[half].
// 256 blocks: 2x parallelism vs R15's 128.
// ---------------------------------------------------------------------------
__global__ void __launch_bounds__(256) offset_conv_kernel(const float* __restrict__ x,
                                                          const float* __restrict__ ow) {
    __shared__ float w_s[64 * 180];
    int tid = threadIdx.x;
    int blk = blockIdx.x;                 // 0..255
    int half = blk & 1;
    int gid = (blk >> 1) * 256 + tid;
    int b   = gid >> 12;
    int rem = gid & 4095;
    int ho  = rem >> 6, wo = rem & 63;

    unsigned long long acc2[10];
#pragma unroll
    for (int i = 0; i < 10; i++) acc2[i] = 0ull;

    int xoff[9];
#pragma unroll
    for (int kh = 0; kh < 3; kh++)
#pragma unroll
        for (int kw = 0; kw < 3; kw++) {
            int y = ho - 1 + kh, xx = wo - 1 + kw;
            bool v = ((unsigned)y < 64u) && ((unsigned)xx < 64u);
            xoff[kh * 3 + kw] = v ? (y * 64 + xx) : -1;
        }
    const float* xb = x + (size_t)b * C_ * HW_;

    int cbase = half * 128;
    for (int c0 = cbase; c0 < cbase + 128; c0 += 64) {
        __syncthreads();
        for (int i = tid; i < 64 * 180; i += 256) {
            int cc = i / 180, r = i % 180, tap = r / 20, ch = r % 20;
            w_s[i] = (ch < 18) ? ow[((size_t)ch * C_ + (c0 + cc)) * K_ + tap] : 0.f;
        }
        __syncthreads();
        for (int cc = 0; cc < 64; cc++) {
            const float* xp = xb + (size_t)(c0 + cc) * HW_;
            float xv[9];
#pragma unroll
            for (int t = 0; t < 9; t++) xv[t] = (xoff[t] >= 0) ? xp[xoff[t]] : 0.f;
            const float* wb = &w_s[cc * 180];
#pragma unroll
            for (int t = 0; t < 9; t++) {
                unsigned long long v2 = pack2(xv[t], xv[t]);
#pragma unroll
                for (int q = 0; q < 5; q++) {
                    ulonglong2 w2 = *(const ulonglong2*)(wb + t * 20 + q * 4);
                    fma2(acc2[q * 2],     v2, w2.x);
                    fma2(acc2[q * 2 + 1], v2, w2.y);
                }
            }
        }
    }
    float* gp = g_offpart[half];
#pragma unroll
    for (int j = 0; j < 9; j++) {
        float lo, hi;
        unpack2(lo, hi, acc2[j]);
        gp[((size_t)b * OCF_ + 2 * j)     * HW_ + rem] = lo;
        gp[((size_t)b * OCF_ + 2 * j + 1) * HW_ + rem] = hi;
    }
}

// ---------------------------------------------------------------------------
// Kernel 3: gather — sums the two offset partials in the samp stage; rest is
// R14/R15 verbatim (coalesced g_xt channel rows -> g_patch).
// ---------------------------------------------------------------------------
__global__ void __launch_bounds__(256) gather_kernel() {
    __shared__ float samp_w[128 * 4];
    __shared__ int   samp_i[128 * 4];
    int tid = threadIdx.x;
    int blk = blockIdx.x;                 // 0..2303
    int k     = blk % 9;
    int slice = blk / 9;
    int b  = slice >> 5;
    int rp = slice & 31;
    int ho0 = rp * 2;

    if (tid < 128) {
        int p = tid;
        int ho = ho0 + (p >> 6), wo2 = p & 63;
        size_t obase = (size_t)b * OCF_ * HW_ + ho * 64 + wo2;
        float dy = g_offpart[0][obase + (size_t)(2 * k) * HW_]
                 + g_offpart[1][obase + (size_t)(2 * k) * HW_];
        float dx = g_offpart[0][obase + (size_t)(2 * k + 1) * HW_]
                 + g_offpart[1][obase + (size_t)(2 * k + 1) * HW_];
        float sy = (float)(ho - 1 + k / 3) + dy;
        float sx = (float)(wo2 - 1 + k % 3) + dx;
        float y0f = floorf(sy), x0f = floorf(sx);
        float ly = sy - y0f, lx = sx - x0f;
        int y0 = (int)y0f, x0 = (int)x0f;
#pragma unroll
        for (int j = 0; j < 4; j++) {
            int yc = y0 + (j >> 1), xc = x0 + (j & 1);
            float wy = (j >> 1) ? ly : 1.f - ly;
            float wx = (j & 1)  ? lx : 1.f - lx;
            bool v = ((unsigned)yc < 64u) && ((unsigned)xc < 64u);
            samp_w[p * 4 + j] = v ? wy * wx : 0.f;
            samp_i[p * 4 + j] = min(max(yc, 0), 63) * 64 + min(max(xc, 0), 63);
        }
    }
    __syncthreads();

    const char* xtb = (const char*)g_xt + (size_t)b * HW_ * 512;
    int p8 = tid >> 3, sub = tid & 7;

#pragma unroll 1
    for (int pp = 0; pp < 4; pp++) {
        int p = pp * 32 + p8;
        const float4 wv = *(const float4*)(samp_w + p * 4);
        const int4   iv = *(const int4*)(samp_i + p * 4);
        const char* r0 = xtb + (size_t)iv.x * 512 + sub * 16;
        const char* r1 = xtb + (size_t)iv.y * 512 + sub * 16;
        const char* r2 = xtb + (size_t)iv.z * 512 + sub * 16;
        const char* r3 = xtb + (size_t)iv.w * 512 + sub * 16;
#pragma unroll
        for (int ci = 0; ci < 4; ci++) {
            uint4 cA = *(const uint4*)(r0 + ci * 128);
            uint4 cB = *(const uint4*)(r1 + ci * 128);
            uint4 cC = *(const uint4*)(r2 + ci * 128);
            uint4 cD = *(const uint4*)(r3 + ci * 128);
            float v[8];
#pragma unroll
            for (int i = 0; i < 8; i++) v[i] = 0.f;
            const uint4* crs[4] = { &cA, &cB, &cC, &cD };
#pragma unroll
            for (int j = 0; j < 4; j++) {
                const __half2* h = (const __half2*)crs[j];
                float wj = (&wv.x)[j];
#pragma unroll
                for (int q = 0; q < 4; q++) {
                    float2 f = __half22float2(h[q]);
                    v[2 * q]     += wj * f.x;
                    v[2 * q + 1] += wj * f.y;
                }
            }
            uint32_t hp[4];
#pragma unroll
            for (int q = 0; q < 4; q++) {
                __half2 h2 = __floats2half2_rn(v[2 * q], v[2 * q + 1]);
                hp[q] = *(uint32_t*)&h2;
            }
            char* dst = (char*)(g_patch + ((size_t)slice * NCHUNK + k * 4 + ci) * 8192);
            *(uint4*)(dst + swz((uint32_t)(p * 128 + sub * 16))) = *(uint4*)hp;
        }
    }
}

// ---------------------------------------------------------------------------
// Kernel 4: dense GEMM (R15 verbatim): o-split x2, 512 CTAs, 2 CTAs/SM.
// ---------------------------------------------------------------------------
__global__ void __launch_bounds__(256, 2) gemm_kernel() {
    extern __shared__ char smem[];
    uint32_t sb = smem_u32(smem);
    int tid = threadIdx.x, wid = tid >> 5, lane = tid & 31;
    int blk = blockIdx.x;                 // 0..511
    int slice = blk >> 1;
    int half  = blk & 1;
    int b   = slice >> 5;
    int rp  = slice & 31;
    int pos0 = rp * 128;
    int wo = wid >> 1;
    int wp = wid & 1;
    int mat = lane >> 3, mr = lane & 7;

    const char* psrc = (const char*)(g_patch + (size_t)slice * NCHUNK * 8192);

    float acc[2][8][4];
#pragma unroll
    for (int i = 0; i < 2; i++)
#pragma unroll
        for (int j = 0; j < 8; j++)
#pragma unroll
            for (int q = 0; q < 4; q++) acc[i][j][q] = 0.f;

    auto prefetch = [&](int chunk, int st) {
        uint32_t sdst = sb + (uint32_t)st * STAGE_BYTES;
        const char* ps = psrc + (size_t)chunk * 16384;
        const char* ws = (const char*)g_wsw + (size_t)chunk * 32768 + (size_t)half * 16384;
#pragma unroll
        for (int i = 0; i < 4; i++)
            CP16(sdst + OFF_P + (tid + i * 256) * 16, ps + (tid + i * 256) * 16);
#pragma unroll
        for (int i = 0; i < 4; i++)
            CP16(sdst + OFF_W + (tid + i * 256) * 16, ws + (tid + i * 256) * 16);
        CP_COMMIT();
    };

    prefetch(0, 0);
    prefetch(1, 1);

#pragma unroll 1
    for (int chunk = 0; chunk < NCHUNK; chunk++) {
        int st = chunk % NSTAGE;
        CP_WAIT(1);
        __syncthreads();

        if (chunk + 2 < NCHUNK)
            prefetch(chunk + 2, (chunk + 2) % NSTAGE);

        uint32_t cur = sb + (uint32_t)st * STAGE_BYTES;
#pragma unroll
        for (int ks = 0; ks < 4; ks++) {
            uint32_t af[2][4];
#pragma unroll
            for (int mt = 0; mt < 2; mt++) {
                uint32_t byte = (uint32_t)((wo * 32 + mt * 16 + (mat & 1) * 8 + mr) * 128
                                           + ks * 32 + (mat >> 1) * 16);
                ldsm4(af[mt], cur + OFF_W + swz(byte));
            }
            uint32_t bf[4][4];
#pragma unroll
            for (int nb = 0; nb < 4; nb++) {
                uint32_t byte = (uint32_t)((wp * 64 + nb * 16 + (mat >> 1) * 8 + mr) * 128
                                           + ks * 32 + (mat & 1) * 16);
                ldsm4(bf[nb], cur + OFF_P + swz(byte));
            }
#pragma unroll
            for (int nb = 0; nb < 4; nb++)
#pragma unroll
                for (int hf = 0; hf < 2; hf++)
#pragma unroll
                    for (int mt = 0; mt < 2; mt++)
                        mma_f16(acc[mt][2 * nb + hf], af[mt], bf[nb] + 2 * hf);
        }
        __syncthreads();
    }

    int l4 = lane >> 2, l2 = (lane & 3) * 2;
#pragma unroll
    for (int mt = 0; mt < 2; mt++) {
#pragma unroll
        for (int nt = 0; nt < 8; nt++) {
            int o = half * 128 + wo * 32 + mt * 16 + l4;
            int p = wp * 64 + nt * 8 + l2;
            float* dst = g_y + ((size_t)(b * CO_ + o)) * HW_ + pos0 + p;
            *(float2*)dst = make_float2(acc[mt][nt][0], acc[mt][nt][1]);
            *(float2*)(dst + (size_t)8 * HW_) = make_float2(acc[mt][nt][2], acc[mt][nt][3]);
        }
    }
}

// ---------------------------------------------------------------------------
// Kernel 5: channel attention (unchanged)
// ---------------------------------------------------------------------------
__global__ void __launch_bounds__(256) attn_kernel(float* __restrict__ out) {
    int bo = blockIdx.x;
    const float4* yp = (const float4*)(g_y + (size_t)bo * HW_);
    int tid = threadIdx.x;

    float s = 0.f, s2 = 0.f;
    float4 v[4];
#pragma unroll
    for (int i = 0; i < 4; i++) {
        v[i] = yp[tid + i * 256];
        s  += v[i].x + v[i].y + v[i].z + v[i].w;
        s2 += v[i].x * v[i].x + v[i].y * v[i].y + v[i].z * v[i].z + v[i].w * v[i].w;
    }
#pragma unroll
    for (int off = 16; off; off >>= 1) {
        s  += __shfl_down_sync(0xffffffffu, s,  off);
        s2 += __shfl_down_sync(0xffffffffu, s2, off);
    }
    __shared__ float rs[8], rs2[8];
    __shared__ float sa;
    int lane = tid & 31, w = tid >> 5;
    if (lane == 0) { rs[w] = s; rs2[w] = s2; }
    __syncthreads();
    if (tid == 0) {
        float S = 0.f, S2 = 0.f;
#pragma unroll
        for (int i = 0; i < 8; i++) { S += rs[i]; S2 += rs2[i]; }
        float mean = S * (1.f / 4096.f);
        float var  = (S2 - S * S * (1.f / 4096.f)) * (1.f / 4095.f);
        float sd   = sqrtf(fmaxf(var, 0.f));
        sa = 1.f / (1.f + expf(-(mean + sd)));
    }
    __syncthreads();
    float a = sa;
    float4* op = (float4*)(out + (size_t)bo * HW_);
#pragma unroll
    for (int i = 0; i < 4; i++) {
        float4 u = v[i];
        u.x *= a; u.y *= a; u.z *= a; u.w *= a;
        op[tid + i * 256] = u;
    }
}

// ---------------------------------------------------------------------------
extern "C" void kernel_launch(void* const* d_in, const int* in_sizes, int n_in,
                              void* d_out, int out_size) {
    const float* x  = (const float*)d_in[0];
    const float* ow = (const float*)d_in[1];
    const float* dw = (const float*)d_in[2];
    float* out = (float*)d_out;

    cudaFuncSetAttribute(gemm_kernel,
                         cudaFuncAttributeMaxDynamicSharedMemorySize, SMEM_TOTAL);

    wt_prep_kernel<<<(K_ * CO_ * C_) / 256, 256>>>(dw);
    xt_kernel<<<B_ * 64, 256>>>(x);
    offset_conv_kernel<<<256, 256>>>(x, ow);
    gather_kernel<<<256 * K_, 256>>>();
    gemm_kernel<<<512, 256, SMEM_TOTAL>>>();
    attn_kernel<<<B_ * CO_, 256>>>(out);
}